// round 7
// baseline (speedup 1.0000x reference)
#include <cuda_runtime.h>

// TransOp expm: out[b, s*8..] = expm(A_{b,s}) @ x[b, s*8..]
// A_{b,s} = sum_m c[b,m] * psi[m,s,:,:]  (8x8).
//
// BATCH-PACKED f32x2: each f32x2 holds {problem b0, problem b1}. A thread
// pair (h=0,1) handles two problems jointly; thread h owns rows 4h..4h+3 of
// both A matrices (32 ull). The matvec multiplier {v_b0[k], v_b1[k]} is
// naturally packed, so the main loop is pure FFMA2 — no dup/unpack MOVs.
// Columns are stored own-slots-first (k = (q+4h)&7) so the partner half of v
// (4 ull via shfl.xor 1) is only needed for the last 4 FMAs of each row.
//
// Taylor action, warp-uniform (order m, reps r) from warp-max ||A||_inf:
//   <=2.6: m=11  <=3.6: m=13  <=4.8: m=16  <=6.0: m=18  <=7.2: m=21
//   else: r = ceil(wmax/3.2), m=13, A scaled by 1/r.
// Horner: v = b; for j=m..1: v = b + (A v)/j.

typedef unsigned long long ull;

#define BDIM 256

__constant__ float INV_TAB[32] = {
    0.0f,    1.0f,    1.0f/2,  1.0f/3,  1.0f/4,  1.0f/5,
    1.0f/6,  1.0f/7,  1.0f/8,  1.0f/9,  1.0f/10, 1.0f/11,
    1.0f/12, 1.0f/13, 1.0f/14, 1.0f/15, 1.0f/16, 1.0f/17,
    1.0f/18, 1.0f/19, 1.0f/20, 1.0f/21, 1.0f/22, 1.0f/23,
    1.0f/24, 1.0f/25, 1.0f/26, 1.0f/27, 1.0f/28, 1.0f/29,
    1.0f/30, 1.0f/31
};

__device__ __forceinline__ ull dup2(float v) {
    ull r; asm("mov.b64 %0, {%1,%1};" : "=l"(r) : "f"(v)); return r;
}
__device__ __forceinline__ ull pack2(float lo, float hi) {
    ull r; asm("mov.b64 %0, {%1,%2};" : "=l"(r) : "f"(lo), "f"(hi)); return r;
}
__device__ __forceinline__ void unpack2(ull v, float& lo, float& hi) {
    asm("mov.b64 {%0,%1}, %2;" : "=f"(lo), "=f"(hi) : "l"(v));
}
__device__ __forceinline__ ull fma2(ull a, ull b, ull c) {
    ull d; asm("fma.rn.f32x2 %0, %1, %2, %3;" : "=l"(d) : "l"(a), "l"(b), "l"(c)); return d;
}
__device__ __forceinline__ ull mul2(ull a, ull b) {
    ull d; asm("mul.rn.f32x2 %0, %1, %2;" : "=l"(d) : "l"(a), "l"(b)); return d;
}
__device__ __forceinline__ ull add2(ull a, ull b) {
    ull d; asm("add.rn.f32x2 %0, %1, %2;" : "=l"(d) : "l"(a), "l"(b)); return d;
}

__global__ __launch_bounds__(BDIM, 2) void transop_expm_kernel(
    const float* __restrict__ x,
    const float* __restrict__ c,
    const float* __restrict__ psi,
    float* __restrict__ out)
{
    // psi slice for this CTA's s, each scalar duplicated into both f32x2
    // lanes so the batch-packed A build is straight LDS.64 + FFMA2.
    __shared__ ull psd[16][64];          // 8 KB

    const int s = blockIdx.x & 63;
    const int t = threadIdx.x;
    const int h = t & 1;                 // row-half owner within the pair
    const int p = t >> 1;                // pair index 0..127
    const int b0 = (blockIdx.x >> 6) * BDIM + 2 * p;   // 256 problems per CTA
    const int b1 = b0 + 1;

    // Stage psi (duplicated): 256 threads x one float4 -> 4 ull each.
    {
        const int m = t >> 4;            // 0..15
        const int j = (t & 15) << 2;     // 0,4,...,60 : linear row*8+k
        const float4 v = *reinterpret_cast<const float4*>(psi + ((m * 64 + s) << 6) + j);
        psd[m][j + 0] = dup2(v.x);
        psd[m][j + 1] = dup2(v.y);
        psd[m][j + 2] = dup2(v.z);
        psd[m][j + 3] = dup2(v.w);
    }
    __syncthreads();

    // c packed over the batch pair: cm2[m] = {c[b0][m], c[b1][m]}.
    ull cm2[16];
    {
        const float4* c0 = reinterpret_cast<const float4*>(c + b0 * 16);
        const float4* c1 = reinterpret_cast<const float4*>(c + b1 * 16);
#pragma unroll
        for (int q = 0; q < 4; ++q) {
            const float4 a = c0[q];
            const float4 bq = c1[q];
            cm2[q * 4 + 0] = pack2(a.x, bq.x);
            cm2[q * 4 + 1] = pack2(a.y, bq.y);
            cm2[q * 4 + 2] = pack2(a.z, bq.z);
            cm2[q * 4 + 3] = pack2(a.w, bq.w);
        }
    }

    // Batch-packed A build for rows 4h..4h+3 of both problems.
    // Storage permutation: A2[r*8+q] = A[4h+r][(q+4h)&7]  (own columns first).
    ull A2[32];
    {
        int idx[32];                      // smem offsets (uniform per h)
#pragma unroll
        for (int r = 0; r < 4; ++r)
#pragma unroll
            for (int q = 0; q < 8; ++q)
                idx[r * 8 + q] = (4 * h + r) * 8 + ((q + 4 * h) & 7);

#pragma unroll
        for (int i = 0; i < 32; ++i) A2[i] = mul2(cm2[0], psd[0][idx[i]]);
#pragma unroll
        for (int m = 1; m < 16; ++m) {
#pragma unroll
            for (int i = 0; i < 32; ++i)
                A2[i] = fma2(cm2[m], psd[m][idx[i]], A2[i]);
        }
    }

    // Infinity norm over this thread's 4 rows of BOTH problems (column
    // permutation does not change row sums). Warp reduce -> uniform tier.
    float ninf = 0.0f;
    {
        const ull mask = 0x7FFFFFFF7FFFFFFFULL;
#pragma unroll
        for (int r = 0; r < 4; ++r) {
            ull acc = A2[r * 8] & mask;
#pragma unroll
            for (int k = 1; k < 8; ++k) acc = add2(acc, A2[r * 8 + k] & mask);
            float a0, a1; unpack2(acc, a0, a1);
            ninf = fmaxf(ninf, fmaxf(a0, a1));
        }
    }
    const float wmax = __uint_as_float(
        __reduce_max_sync(0xffffffffu, __float_as_uint(ninf)));

    int m_ord, r;
    if (wmax <= 2.6f)       { m_ord = 11; r = 1; }
    else if (wmax <= 3.6f)  { m_ord = 13; r = 1; }
    else if (wmax <= 4.8f)  { m_ord = 16; r = 1; }
    else if (wmax <= 6.0f)  { m_ord = 18; r = 1; }
    else if (wmax <= 7.2f)  { m_ord = 21; r = 1; }
    else {
        r = (int)ceilf(wmax * (1.0f / 3.2f));
        if (r > 31) r = 31;
        m_ord = 13;
    }

    if (r > 1) {
        const ull s2 = dup2(INV_TAB[r]);
#pragma unroll
        for (int i = 0; i < 32; ++i) A2[i] = mul2(A2[i], s2);
    }

    // Own 4 elements (global rows 4h..4h+3) of x for both problems, packed.
    ull v2[4];
    {
        const float4 xa = *reinterpret_cast<const float4*>(x + b0 * 512 + s * 8 + 4 * h);
        const float4 xb = *reinterpret_cast<const float4*>(x + b1 * 512 + s * 8 + 4 * h);
        v2[0] = pack2(xa.x, xb.x);
        v2[1] = pack2(xa.y, xb.y);
        v2[2] = pack2(xa.z, xb.z);
        v2[3] = pack2(xa.w, xb.w);
    }

    // r repetitions of order-m Horner Taylor action. Pure FFMA2 inner loop.
    for (int rr = 0; rr < r; ++rr) {
        const ull b2_0 = v2[0], b2_1 = v2[1], b2_2 = v2[2], b2_3 = v2[3];
        for (int j = m_ord; j > 0; --j) {
            // Partner half of v (its own-ordered 4 ull), in flight while the
            // own-column FMAs below execute.
            const ull q0 = __shfl_xor_sync(0xffffffffu, v2[0], 1);
            const ull q1 = __shfl_xor_sync(0xffffffffu, v2[1], 1);
            const ull q2 = __shfl_xor_sync(0xffffffffu, v2[2], 1);
            const ull q3 = __shfl_xor_sync(0xffffffffu, v2[3], 1);

            ull w0 = mul2(A2[0],  v2[0]);
            ull w1 = mul2(A2[8],  v2[0]);
            ull w2 = mul2(A2[16], v2[0]);
            ull w3 = mul2(A2[24], v2[0]);
#pragma unroll
            for (int k = 1; k < 4; ++k) {
                w0 = fma2(A2[0  + k], v2[k], w0);
                w1 = fma2(A2[8  + k], v2[k], w1);
                w2 = fma2(A2[16 + k], v2[k], w2);
                w3 = fma2(A2[24 + k], v2[k], w3);
            }
            w0 = fma2(A2[4],  q0, w0); w0 = fma2(A2[5],  q1, w0);
            w0 = fma2(A2[6],  q2, w0); w0 = fma2(A2[7],  q3, w0);
            w1 = fma2(A2[12], q0, w1); w1 = fma2(A2[13], q1, w1);
            w1 = fma2(A2[14], q2, w1); w1 = fma2(A2[15], q3, w1);
            w2 = fma2(A2[20], q0, w2); w2 = fma2(A2[21], q1, w2);
            w2 = fma2(A2[22], q2, w2); w2 = fma2(A2[23], q3, w2);
            w3 = fma2(A2[28], q0, w3); w3 = fma2(A2[29], q1, w3);
            w3 = fma2(A2[30], q2, w3); w3 = fma2(A2[31], q3, w3);

            const ull sj = dup2(INV_TAB[j]);
            v2[0] = fma2(w0, sj, b2_0);
            v2[1] = fma2(w1, sj, b2_1);
            v2[2] = fma2(w2, sj, b2_2);
            v2[3] = fma2(w3, sj, b2_3);
        }
    }

    // Store: each ull splits into one element of b0's row and one of b1's.
    {
        float lo, hi;
        float* o0 = out + b0 * 512 + s * 8 + 4 * h;
        float* o1 = out + b1 * 512 + s * 8 + 4 * h;
        unpack2(v2[0], lo, hi); o0[0] = lo; o1[0] = hi;
        unpack2(v2[1], lo, hi); o0[1] = lo; o1[1] = hi;
        unpack2(v2[2], lo, hi); o0[2] = lo; o1[2] = hi;
        unpack2(v2[3], lo, hi); o0[3] = lo; o1[3] = hi;
    }
}

extern "C" void kernel_launch(void* const* d_in, const int* in_sizes, int n_in,
                              void* d_out, int out_size)
{
    const float* x   = (const float*)d_in[0];   // (B, 512)
    const float* c   = (const float*)d_in[1];   // (B, 16)
    const float* psi = (const float*)d_in[2];   // (16, 64, 8, 8)
    float* out = (float*)d_out;                 // (B, 512)

    const int B = in_sizes[0] / 512;            // 8192
    // Each CTA: one s, 256 problems (128 thread pairs x 2 batch-packed).
    const dim3 grid((B / BDIM) * 64);           // 2048 CTAs
    transop_expm_kernel<<<grid, BDIM>>>(x, c, psi, out);
}

// round 8
// speedup vs baseline: 1.0510x; 1.0510x over previous
#include <cuda_runtime.h>

// TransOp expm: out[b, s*8..] = expm(A_{b,s}) @ x[b, s*8..]
// A_{b,s} = sum_m c[b,m] * psi[m,s,:,:]  (8x8).
//
// BATCH-PACKED f32x2: each f32x2 holds {problem b0, problem b1}. A thread
// pair (h=0,1) handles two problems jointly; thread h owns rows 4h..4h+3 of
// both A matrices (32 ull). Multipliers {v_b0[k], v_b1[k]} are naturally
// packed -> pure-FFMA2 inner loop, no dup/unpack MOVs. Partner half of v via
// 4x 64-bit shfl.xor per step.
//
// A-build addressing: the column permutation k=(q+4h)&7 is realized as TWO
// base pointers with constant offsets (own-column group & partner-column
// group are each contiguous), so every LDS has a compile-time offset.
//
// Taylor action, warp-uniform (order m, reps r) from warp-max ||A||_inf:
//   <=2.6: m=10  <=3.6: m=12  <=4.8: m=14  <=6.0: m=16  <=7.2: m=19
//   else: r = ceil(wmax/3.2), m=13, A scaled by 1/r.
// Horner: v = b; for j=m..1: v = b + (A v)/j.

typedef unsigned long long ull;

#define BDIM 256

__constant__ float2 INV2[32] = {
    {0.0f,0.0f},       {1.0f,1.0f},       {1.0f/2,1.0f/2},   {1.0f/3,1.0f/3},
    {1.0f/4,1.0f/4},   {1.0f/5,1.0f/5},   {1.0f/6,1.0f/6},   {1.0f/7,1.0f/7},
    {1.0f/8,1.0f/8},   {1.0f/9,1.0f/9},   {1.0f/10,1.0f/10}, {1.0f/11,1.0f/11},
    {1.0f/12,1.0f/12}, {1.0f/13,1.0f/13}, {1.0f/14,1.0f/14}, {1.0f/15,1.0f/15},
    {1.0f/16,1.0f/16}, {1.0f/17,1.0f/17}, {1.0f/18,1.0f/18}, {1.0f/19,1.0f/19},
    {1.0f/20,1.0f/20}, {1.0f/21,1.0f/21}, {1.0f/22,1.0f/22}, {1.0f/23,1.0f/23},
    {1.0f/24,1.0f/24}, {1.0f/25,1.0f/25}, {1.0f/26,1.0f/26}, {1.0f/27,1.0f/27},
    {1.0f/28,1.0f/28}, {1.0f/29,1.0f/29}, {1.0f/30,1.0f/30}, {1.0f/31,1.0f/31}
};

__device__ __forceinline__ ull dup2(float v) {
    ull r; asm("mov.b64 %0, {%1,%1};" : "=l"(r) : "f"(v)); return r;
}
__device__ __forceinline__ ull pack2(float lo, float hi) {
    ull r; asm("mov.b64 %0, {%1,%2};" : "=l"(r) : "f"(lo), "f"(hi)); return r;
}
__device__ __forceinline__ void unpack2(ull v, float& lo, float& hi) {
    asm("mov.b64 {%0,%1}, %2;" : "=f"(lo), "=f"(hi) : "l"(v));
}
__device__ __forceinline__ ull fma2(ull a, ull b, ull c) {
    ull d; asm("fma.rn.f32x2 %0, %1, %2, %3;" : "=l"(d) : "l"(a), "l"(b), "l"(c)); return d;
}
__device__ __forceinline__ ull mul2(ull a, ull b) {
    ull d; asm("mul.rn.f32x2 %0, %1, %2;" : "=l"(d) : "l"(a), "l"(b)); return d;
}
__device__ __forceinline__ ull add2(ull a, ull b) {
    ull d; asm("add.rn.f32x2 %0, %1, %2;" : "=l"(d) : "l"(a), "l"(b)); return d;
}

__global__ __launch_bounds__(BDIM, 2) void transop_expm_kernel(
    const float* __restrict__ x,
    const float* __restrict__ c,
    const float* __restrict__ psi,
    float* __restrict__ out)
{
    // psi slice for this CTA's s, each scalar duplicated into both f32x2
    // lanes so the batch-packed A build is straight LDS + FFMA2.
    __shared__ ull psd[16][64];          // 8 KB, [m][row*8+col]

    const int s = blockIdx.x & 63;
    const int t = threadIdx.x;
    const int h = t & 1;                 // row-half owner within the pair
    const int p = t >> 1;                // pair index 0..127
    const int b0 = (blockIdx.x >> 6) * BDIM + 2 * p;
    const int b1 = b0 + 1;

    // Stage psi (duplicated): 256 threads x one float4 -> 4 ull each.
    {
        const int m = t >> 4;            // 0..15
        const int j = (t & 15) << 2;     // 0,4,...,60 : linear row*8+col
        const float4 v = *reinterpret_cast<const float4*>(psi + ((m * 64 + s) << 6) + j);
        psd[m][j + 0] = dup2(v.x);
        psd[m][j + 1] = dup2(v.y);
        psd[m][j + 2] = dup2(v.z);
        psd[m][j + 3] = dup2(v.w);
    }
    __syncthreads();

    // c packed over the batch pair: cm2[m] = {c[b0][m], c[b1][m]}.
    ull cm2[16];
    {
        const float4* c0 = reinterpret_cast<const float4*>(c + b0 * 16);
        const float4* c1 = reinterpret_cast<const float4*>(c + b1 * 16);
#pragma unroll
        for (int q = 0; q < 4; ++q) {
            const float4 a = c0[q];
            const float4 bq = c1[q];
            cm2[q * 4 + 0] = pack2(a.x, bq.x);
            cm2[q * 4 + 1] = pack2(a.y, bq.y);
            cm2[q * 4 + 2] = pack2(a.z, bq.z);
            cm2[q * 4 + 3] = pack2(a.w, bq.w);
        }
    }

    // Batch-packed A build for rows 4h..4h+3 of both problems.
    // Storage: A2[r*8+q] = A[4h+r][(q+4h)&7]  (own columns first).
    // Own group (q=0..3):      col 4h+q      -> base p0 = row 4h, col 4h
    // Partner group (q=4..7):  col (4-4h)+q' -> base p1 = row 4h, col 4-4h
    // Both groups are 4 contiguous ull -> two LDS.128 each, constant offsets.
    const ulonglong2* q0 = reinterpret_cast<const ulonglong2*>(
        &psd[0][0] + 36 * h);            // 32h (row) + 4h (col)
    const ulonglong2* q1 = reinterpret_cast<const ulonglong2*>(
        &psd[0][0] + 28 * h + 4);        // 32h (row) + 4-4h (col)

    ull A2[32];
#pragma unroll
    for (int i = 0; i < 32; ++i) A2[i] = 0;  // replaced by first-m mul below

#pragma unroll
    for (int m = 0; m < 16; ++m) {
        const ull cd = cm2[m];
#pragma unroll
        for (int r = 0; r < 4; ++r) {
            const ulonglong2 oa = q0[m * 32 + r * 4 + 0];   // own cols q=0,1
            const ulonglong2 ob = q0[m * 32 + r * 4 + 1];   // own cols q=2,3
            const ulonglong2 pa = q1[m * 32 + r * 4 + 0];   // partner q=4,5
            const ulonglong2 pb = q1[m * 32 + r * 4 + 1];   // partner q=6,7
            if (m == 0) {
                A2[r * 8 + 0] = mul2(cd, oa.x);
                A2[r * 8 + 1] = mul2(cd, oa.y);
                A2[r * 8 + 2] = mul2(cd, ob.x);
                A2[r * 8 + 3] = mul2(cd, ob.y);
                A2[r * 8 + 4] = mul2(cd, pa.x);
                A2[r * 8 + 5] = mul2(cd, pa.y);
                A2[r * 8 + 6] = mul2(cd, pb.x);
                A2[r * 8 + 7] = mul2(cd, pb.y);
            } else {
                A2[r * 8 + 0] = fma2(cd, oa.x, A2[r * 8 + 0]);
                A2[r * 8 + 1] = fma2(cd, oa.y, A2[r * 8 + 1]);
                A2[r * 8 + 2] = fma2(cd, ob.x, A2[r * 8 + 2]);
                A2[r * 8 + 3] = fma2(cd, ob.y, A2[r * 8 + 3]);
                A2[r * 8 + 4] = fma2(cd, pa.x, A2[r * 8 + 4]);
                A2[r * 8 + 5] = fma2(cd, pa.y, A2[r * 8 + 5]);
                A2[r * 8 + 6] = fma2(cd, pb.x, A2[r * 8 + 6]);
                A2[r * 8 + 7] = fma2(cd, pb.y, A2[r * 8 + 7]);
            }
        }
    }

    // Infinity norm over this thread's 4 rows of BOTH problems (column
    // permutation does not change row sums). Warp reduce -> uniform tier.
    float ninf = 0.0f;
    {
        const ull mask = 0x7FFFFFFF7FFFFFFFULL;
#pragma unroll
        for (int r = 0; r < 4; ++r) {
            ull acc = A2[r * 8] & mask;
#pragma unroll
            for (int k = 1; k < 8; ++k) acc = add2(acc, A2[r * 8 + k] & mask);
            float a0, a1; unpack2(acc, a0, a1);
            ninf = fmaxf(ninf, fmaxf(a0, a1));
        }
    }
    const float wmax = __uint_as_float(
        __reduce_max_sync(0xffffffffu, __float_as_uint(ninf)));

    int m_ord, r;
    if (wmax <= 2.6f)       { m_ord = 10; r = 1; }
    else if (wmax <= 3.6f)  { m_ord = 12; r = 1; }
    else if (wmax <= 4.8f)  { m_ord = 14; r = 1; }
    else if (wmax <= 6.0f)  { m_ord = 16; r = 1; }
    else if (wmax <= 7.2f)  { m_ord = 19; r = 1; }
    else {
        r = (int)ceilf(wmax * (1.0f / 3.2f));
        if (r > 31) r = 31;
        m_ord = 13;
    }

    if (r > 1) {
        const ull s2 = *reinterpret_cast<const ull*>(&INV2[r]);
#pragma unroll
        for (int i = 0; i < 32; ++i) A2[i] = mul2(A2[i], s2);
    }

    // Own 4 elements (global rows 4h..4h+3) of x for both problems, packed.
    ull v2[4];
    {
        const float4 xa = *reinterpret_cast<const float4*>(x + b0 * 512 + s * 8 + 4 * h);
        const float4 xb = *reinterpret_cast<const float4*>(x + b1 * 512 + s * 8 + 4 * h);
        v2[0] = pack2(xa.x, xb.x);
        v2[1] = pack2(xa.y, xb.y);
        v2[2] = pack2(xa.z, xb.z);
        v2[3] = pack2(xa.w, xb.w);
    }

    // r repetitions of order-m Horner Taylor action. Pure FFMA2 inner loop.
    for (int rr = 0; rr < r; ++rr) {
        const ull b2_0 = v2[0], b2_1 = v2[1], b2_2 = v2[2], b2_3 = v2[3];
        for (int j = m_ord; j > 0; --j) {
            // Partner half of v (its own-ordered 4 ull).
            const ull q0v = __shfl_xor_sync(0xffffffffu, v2[0], 1);
            const ull q1v = __shfl_xor_sync(0xffffffffu, v2[1], 1);
            const ull q2v = __shfl_xor_sync(0xffffffffu, v2[2], 1);
            const ull q3v = __shfl_xor_sync(0xffffffffu, v2[3], 1);

            ull w0 = mul2(A2[0],  v2[0]);
            ull w1 = mul2(A2[8],  v2[0]);
            ull w2 = mul2(A2[16], v2[0]);
            ull w3 = mul2(A2[24], v2[0]);
#pragma unroll
            for (int k = 1; k < 4; ++k) {
                w0 = fma2(A2[0  + k], v2[k], w0);
                w1 = fma2(A2[8  + k], v2[k], w1);
                w2 = fma2(A2[16 + k], v2[k], w2);
                w3 = fma2(A2[24 + k], v2[k], w3);
            }
            w0 = fma2(A2[4],  q0v, w0); w0 = fma2(A2[5],  q1v, w0);
            w0 = fma2(A2[6],  q2v, w0); w0 = fma2(A2[7],  q3v, w0);
            w1 = fma2(A2[12], q0v, w1); w1 = fma2(A2[13], q1v, w1);
            w1 = fma2(A2[14], q2v, w1); w1 = fma2(A2[15], q3v, w1);
            w2 = fma2(A2[20], q0v, w2); w2 = fma2(A2[21], q1v, w2);
            w2 = fma2(A2[22], q2v, w2); w2 = fma2(A2[23], q3v, w2);
            w3 = fma2(A2[28], q0v, w3); w3 = fma2(A2[29], q1v, w3);
            w3 = fma2(A2[30], q2v, w3); w3 = fma2(A2[31], q3v, w3);

            const ull sj = *reinterpret_cast<const ull*>(&INV2[j]);
            v2[0] = fma2(w0, sj, b2_0);
            v2[1] = fma2(w1, sj, b2_1);
            v2[2] = fma2(w2, sj, b2_2);
            v2[3] = fma2(w3, sj, b2_3);
        }
    }

    // Store: each ull splits into one element of b0's row and one of b1's.
    {
        float lo, hi;
        float* o0 = out + b0 * 512 + s * 8 + 4 * h;
        float* o1 = out + b1 * 512 + s * 8 + 4 * h;
        unpack2(v2[0], lo, hi); o0[0] = lo; o1[0] = hi;
        unpack2(v2[1], lo, hi); o0[1] = lo; o1[1] = hi;
        unpack2(v2[2], lo, hi); o0[2] = lo; o1[2] = hi;
        unpack2(v2[3], lo, hi); o0[3] = lo; o1[3] = hi;
    }
}

extern "C" void kernel_launch(void* const* d_in, const int* in_sizes, int n_in,
                              void* d_out, int out_size)
{
    const float* x   = (const float*)d_in[0];   // (B, 512)
    const float* c   = (const float*)d_in[1];   // (B, 16)
    const float* psi = (const float*)d_in[2];   // (16, 64, 8, 8)
    float* out = (float*)d_out;                 // (B, 512)

    const int B = in_sizes[0] / 512;            // 8192
    // Each CTA: one s, 256 problems (128 thread pairs x 2 batch-packed).
    const dim3 grid((B / BDIM) * 64);           // 2048 CTAs
    transop_expm_kernel<<<grid, BDIM>>>(x, c, psi, out);
}